// round 6
// baseline (speedup 1.0000x reference)
#include <cuda_runtime.h>
#include <cuda_bf16.h>
#include <cstdint>

#define IN_FEAT   256
#define OUT_FEAT  32
#define MAXN      102400
#define CAP       64             // bucket slots per row (avg degree 16)
#define MAXOVF    4096
#define TM        256            // gemm rows per block
#define NT        256            // gemm threads
#define KCH       32
#define NCHUNK    (IN_FEAT / KCH)
#define SFP       36
#define KP        260
#define SWT_ELEMS (OUT_FEAT * KP)
#define SF_ELEMS  (TM * SFP)
#define SMEM_BYTES ((SWT_ELEMS + 2 * SF_ELEMS) * 4)

__device__ float g_x[MAXN * OUT_FEAT];          // projected features (13 MB)
__device__ int   g_cnt[MAXN];                   // per-row edge counts
__device__ uint2 g_bucket[(size_t)MAXN * CAP];  // (col, val_bits) per row (52 MB)
__device__ int   g_ovf_n;
__device__ int   g_ovf[MAXOVF];

// ---------------------------------------------------------------------------
// helpers
// ---------------------------------------------------------------------------
__device__ __forceinline__ unsigned smem_u32(const void* p) {
    return (unsigned)__cvta_generic_to_shared(p);
}
__device__ __forceinline__ void cp_async16(unsigned dst, const void* src) {
    asm volatile("cp.async.cg.shared.global [%0], [%1], 16;"
                 :: "r"(dst), "l"(src));
}
__device__ __forceinline__ void cp_commit() {
    asm volatile("cp.async.commit_group;");
}
template <int N>
__device__ __forceinline__ void cp_wait() {
    asm volatile("cp.async.wait_group %0;" :: "n"(N));
}
__device__ __forceinline__ unsigned f2tf32(float f) {
    unsigned r;
    asm("cvt.rna.tf32.f32 %0, %1;" : "=r"(r) : "f"(f));
    return r;
}
__device__ __forceinline__ void mma_tf32(float& c0, float& c1, float& c2, float& c3,
                                         unsigned a0, unsigned a1, unsigned a2, unsigned a3,
                                         unsigned b0, unsigned b1) {
    asm volatile("mma.sync.aligned.m16n8k8.row.col.f32.tf32.tf32.f32 "
                 "{%0,%1,%2,%3}, {%4,%5,%6,%7}, {%8,%9}, {%0,%1,%2,%3};"
                 : "+f"(c0), "+f"(c1), "+f"(c2), "+f"(c3)
                 : "r"(a0), "r"(a1), "r"(a2), "r"(a3), "r"(b0), "r"(b1));
}

// ---------------------------------------------------------------------------
// Stage 1: x = feat @ W   (TF32 tensor-core GEMM, unchanged from R5)
// ---------------------------------------------------------------------------
__global__ __launch_bounds__(NT)
void gemm_kernel(const float* __restrict__ feat,
                 const float* __restrict__ weight,
                 int n_nodes) {
    extern __shared__ char smem[];
    unsigned* sWt = (unsigned*)smem;
    float*    sF  = (float*)(smem + SWT_ELEMS * 4);

    const int t    = threadIdx.x;
    const int warp = t >> 5;
    const int lane = t & 31;
    const int gid  = lane >> 2;
    const int tid4 = lane & 3;
    const int row0 = blockIdx.x * TM;

    auto stage = [&](int c, int b) {
        #pragma unroll
        for (int i = 0; i < (TM * 8) / NT; i++) {
            int idx = i * NT + t;
            int r   = idx >> 3;
            int s   = idx & 7;
            int gr  = row0 + r;
            if (gr > n_nodes - 1) gr = n_nodes - 1;
            const float* src = feat + (size_t)gr * IN_FEAT + c * KCH + s * 4;
            cp_async16(smem_u32(&sF[b * SF_ELEMS + r * SFP + s * 4]), src);
        }
        cp_commit();
    };

    stage(0, 0);

    #pragma unroll
    for (int i = 0; i < (IN_FEAT * OUT_FEAT) / NT; i++) {
        int idx = i * NT + t;
        int k = idx >> 5;
        int n = idx & 31;
        sWt[n * KP + k] = f2tf32(weight[idx]);
    }

    float acc[2][4][4];
    #pragma unroll
    for (int m = 0; m < 2; m++)
        #pragma unroll
        for (int n = 0; n < 4; n++)
            #pragma unroll
            for (int i = 0; i < 4; i++) acc[m][n][i] = 0.f;

    #pragma unroll 1
    for (int c = 0; c < NCHUNK; c++) {
        int b = c & 1;
        if (c + 1 < NCHUNK) { stage(c + 1, b ^ 1); cp_wait<1>(); }
        else                { cp_wait<0>(); }
        __syncthreads();

        const float* fb = &sF[b * SF_ELEMS];
        #pragma unroll
        for (int ks = 0; ks < KCH / 8; ks++) {
            int kl = ks * 8;
            int kg = c * KCH + kl;

            unsigned bf[4][2];
            #pragma unroll
            for (int n = 0; n < 4; n++) {
                const unsigned* wp = &sWt[(n * 8 + gid) * KP + kg + tid4];
                bf[n][0] = wp[0];
                bf[n][1] = wp[4];
            }

            unsigned af[2][4];
            #pragma unroll
            for (int m = 0; m < 2; m++) {
                int rb = warp * 32 + m * 16 + gid;
                const float* ap0 = &fb[rb * SFP + kl + tid4];
                const float* ap1 = &fb[(rb + 8) * SFP + kl + tid4];
                af[m][0] = f2tf32(ap0[0]);
                af[m][1] = f2tf32(ap1[0]);
                af[m][2] = f2tf32(ap0[4]);
                af[m][3] = f2tf32(ap1[4]);
            }

            #pragma unroll
            for (int n = 0; n < 4; n++)
                #pragma unroll
                for (int m = 0; m < 2; m++)
                    mma_tf32(acc[m][n][0], acc[m][n][1], acc[m][n][2], acc[m][n][3],
                             af[m][0], af[m][1], af[m][2], af[m][3],
                             bf[n][0], bf[n][1]);
        }
        __syncthreads();
    }

    #pragma unroll
    for (int m = 0; m < 2; m++) {
        int r0 = row0 + warp * 32 + m * 16 + gid;
        #pragma unroll
        for (int n = 0; n < 4; n++) {
            int col = n * 8 + 2 * tid4;
            if (r0 < n_nodes) {
                float2 v = make_float2(acc[m][n][0], acc[m][n][1]);
                *(float2*)(g_x + (size_t)r0 * OUT_FEAT + col) = v;
            }
            if (r0 + 8 < n_nodes) {
                float2 v = make_float2(acc[m][n][2], acc[m][n][3]);
                *(float2*)(g_x + (size_t)(r0 + 8) * OUT_FEAT + col) = v;
            }
        }
    }
}

// ---------------------------------------------------------------------------
// Stage 2a: reset counters
// ---------------------------------------------------------------------------
__global__ void zero_kernel(int n) {
    int i = blockIdx.x * 256 + threadIdx.x;
    if (i < n) g_cnt[i] = 0;
    if (i == 0) g_ovf_n = 0;
}

// ---------------------------------------------------------------------------
// Stage 2b: bucketize edges by destination row (no scan, no sort)
// ---------------------------------------------------------------------------
__global__ __launch_bounds__(256)
void scatter_kernel(const float* __restrict__ vals,
                    const int* __restrict__ erow,
                    const int* __restrict__ ecol,
                    int n_edges) {
    int e = blockIdx.x * 256 + threadIdx.x;
    if (e >= n_edges) return;
    int r = erow[e];
    int pos = atomicAdd(&g_cnt[r], 1);
    if (pos < CAP) {
        g_bucket[(size_t)r * CAP + pos] =
            make_uint2((unsigned)ecol[e], __float_as_uint(vals[e]));
    } else {
        int o = atomicAdd(&g_ovf_n, 1);
        if (o < MAXOVF) g_ovf[o] = e;
    }
}

// ---------------------------------------------------------------------------
// Stage 2c: warp-per-row segment reduce.  lane = output column.
// Pairs loaded once per 32 lanes, broadcast by shuffle; x-gather is one
// fully-utilized 128B line per edge.  Writes every row -> no memset needed.
// ---------------------------------------------------------------------------
__global__ __launch_bounds__(256)
void gather_kernel(float* __restrict__ out, int n_nodes) {
    int w    = (blockIdx.x * 256 + threadIdx.x) >> 5;
    int lane = threadIdx.x & 31;
    if (w >= n_nodes) return;

    int cnt = g_cnt[w];
    if (cnt > CAP) cnt = CAP;
    const uint2* bk = g_bucket + (size_t)w * CAP;

    float acc = 0.f;
    for (int base = 0; base < cnt; base += 32) {
        uint2 p = make_uint2(0u, 0u);
        if (base + lane < cnt) p = bk[base + lane];
        int m = cnt - base; if (m > 32) m = 32;

        int j = 0;
        for (; j + 4 <= m; j += 4) {
            #pragma unroll
            for (int u = 0; u < 4; u++) {
                int   col = __shfl_sync(0xFFFFFFFFu, (int)p.x, j + u);
                float v   = __uint_as_float(__shfl_sync(0xFFFFFFFFu, (int)p.y, j + u));
                acc += v * g_x[(size_t)col * OUT_FEAT + lane];
            }
        }
        for (; j < m; j++) {
            int   col = __shfl_sync(0xFFFFFFFFu, (int)p.x, j);
            float v   = __uint_as_float(__shfl_sync(0xFFFFFFFFu, (int)p.y, j));
            acc += v * g_x[(size_t)col * OUT_FEAT + lane];
        }
    }
    out[(size_t)w * OUT_FEAT + lane] = acc;
}

// ---------------------------------------------------------------------------
// Stage 2d: apply overflow edges (expected count: 0; correctness guarantee)
// ---------------------------------------------------------------------------
__global__ void fixup_kernel(const float* __restrict__ vals,
                             const int* __restrict__ erow,
                             const int* __restrict__ ecol,
                             float* __restrict__ out) {
    int n = g_ovf_n;
    if (n > MAXOVF) n = MAXOVF;
    for (int i = threadIdx.x; i < n * 8; i += 256) {
        int e = g_ovf[i >> 3];
        int q = (i & 7) << 2;
        int r = erow[e], c = ecol[e];
        float v = vals[e];
        #pragma unroll
        for (int k = 0; k < 4; k++)
            atomicAdd(&out[(size_t)r * OUT_FEAT + q + k],
                      v * g_x[(size_t)c * OUT_FEAT + q + k]);
    }
}

// ---------------------------------------------------------------------------
extern "C" void kernel_launch(void* const* d_in, const int* in_sizes, int n_in,
                              void* d_out, int out_size) {
    const float* feat   = (const float*)d_in[0];
    const float* weight = (const float*)d_in[1];
    const float* vals   = (const float*)d_in[2];
    const int*   erow   = (const int*)d_in[3];
    const int*   ecol   = (const int*)d_in[4];
    float* out = (float*)d_out;

    int n_nodes = in_sizes[0] / IN_FEAT;
    int n_edges = in_sizes[2];

    cudaFuncSetAttribute(gemm_kernel,
                         cudaFuncAttributeMaxDynamicSharedMemorySize, SMEM_BYTES);
    int gemm_blocks = (n_nodes + TM - 1) / TM;
    gemm_kernel<<<gemm_blocks, NT, SMEM_BYTES>>>(feat, weight, n_nodes);

    int nb_nodes = (n_nodes + 255) / 256;
    int nb_edges = (n_edges + 255) / 256;
    zero_kernel<<<nb_nodes, 256>>>(n_nodes);
    scatter_kernel<<<nb_edges, 256>>>(vals, erow, ecol, n_edges);

    long long gw = (long long)n_nodes * 32;
    int nb_gather = (int)((gw + 255) / 256);
    gather_kernel<<<nb_gather, 256>>>(out, n_nodes);

    fixup_kernel<<<1, 256>>>(vals, erow, ecol, out);
}

// round 7
// speedup vs baseline: 1.1731x; 1.1731x over previous
#include <cuda_runtime.h>
#include <cuda_bf16.h>
#include <cstdint>

#define IN_FEAT   256
#define OUT_FEAT  32
#define MAXN      102400
#define CAP       64             // bucket slots per row (avg degree 16)
#define MAXOVF    4096
#define TM        256
#define NT        256
#define KCH       32
#define NCHUNK    (IN_FEAT / KCH)
#define SFP       36
#define KP        260
#define SWT_ELEMS (OUT_FEAT * KP)
#define SF_ELEMS  (TM * SFP)
#define SMEM_BYTES ((SWT_ELEMS + 2 * SF_ELEMS) * 4)

__device__ float g_x[MAXN * OUT_FEAT];          // projected features (13 MB)
__device__ int   g_cnt[MAXN];
__device__ uint2 g_bucket[(size_t)MAXN * CAP];  // (col, val_bits) (52 MB)
__device__ int   g_ovf_n;
__device__ int   g_ovf[MAXOVF];

// ---------------------------------------------------------------------------
// helpers
// ---------------------------------------------------------------------------
__device__ __forceinline__ unsigned smem_u32(const void* p) {
    return (unsigned)__cvta_generic_to_shared(p);
}
__device__ __forceinline__ void cp_async16(unsigned dst, const void* src) {
    asm volatile("cp.async.cg.shared.global [%0], [%1], 16;"
                 :: "r"(dst), "l"(src));
}
__device__ __forceinline__ void cp_commit() {
    asm volatile("cp.async.commit_group;");
}
template <int N>
__device__ __forceinline__ void cp_wait() {
    asm volatile("cp.async.wait_group %0;" :: "n"(N));
}
__device__ __forceinline__ unsigned f2tf32(float f) {
    unsigned r;
    asm("cvt.rna.tf32.f32 %0, %1;" : "=r"(r) : "f"(f));
    return r;
}
__device__ __forceinline__ void mma_tf32(float& c0, float& c1, float& c2, float& c3,
                                         unsigned a0, unsigned a1, unsigned a2, unsigned a3,
                                         unsigned b0, unsigned b1) {
    asm volatile("mma.sync.aligned.m16n8k8.row.col.f32.tf32.tf32.f32 "
                 "{%0,%1,%2,%3}, {%4,%5,%6,%7}, {%8,%9}, {%0,%1,%2,%3};"
                 : "+f"(c0), "+f"(c1), "+f"(c2), "+f"(c3)
                 : "r"(a0), "r"(a1), "r"(a2), "r"(a3), "r"(b0), "r"(b1));
}

// ---------------------------------------------------------------------------
// Stage 1: x = feat @ W   (TF32 tensor-core GEMM — unchanged, ~25 us)
// ---------------------------------------------------------------------------
__global__ __launch_bounds__(NT)
void gemm_kernel(const float* __restrict__ feat,
                 const float* __restrict__ weight,
                 int n_nodes) {
    extern __shared__ char smem[];
    unsigned* sWt = (unsigned*)smem;
    float*    sF  = (float*)(smem + SWT_ELEMS * 4);

    const int t    = threadIdx.x;
    const int warp = t >> 5;
    const int lane = t & 31;
    const int gid  = lane >> 2;
    const int tid4 = lane & 3;
    const int row0 = blockIdx.x * TM;

    auto stage = [&](int c, int b) {
        #pragma unroll
        for (int i = 0; i < (TM * 8) / NT; i++) {
            int idx = i * NT + t;
            int r   = idx >> 3;
            int s   = idx & 7;
            int gr  = row0 + r;
            if (gr > n_nodes - 1) gr = n_nodes - 1;
            const float* src = feat + (size_t)gr * IN_FEAT + c * KCH + s * 4;
            cp_async16(smem_u32(&sF[b * SF_ELEMS + r * SFP + s * 4]), src);
        }
        cp_commit();
    };

    stage(0, 0);

    #pragma unroll
    for (int i = 0; i < (IN_FEAT * OUT_FEAT) / NT; i++) {
        int idx = i * NT + t;
        int k = idx >> 5;
        int n = idx & 31;
        sWt[n * KP + k] = f2tf32(weight[idx]);
    }

    float acc[2][4][4];
    #pragma unroll
    for (int m = 0; m < 2; m++)
        #pragma unroll
        for (int n = 0; n < 4; n++)
            #pragma unroll
            for (int i = 0; i < 4; i++) acc[m][n][i] = 0.f;

    #pragma unroll 1
    for (int c = 0; c < NCHUNK; c++) {
        int b = c & 1;
        if (c + 1 < NCHUNK) { stage(c + 1, b ^ 1); cp_wait<1>(); }
        else                { cp_wait<0>(); }
        __syncthreads();

        const float* fb = &sF[b * SF_ELEMS];
        #pragma unroll
        for (int ks = 0; ks < KCH / 8; ks++) {
            int kl = ks * 8;
            int kg = c * KCH + kl;

            unsigned bf[4][2];
            #pragma unroll
            for (int n = 0; n < 4; n++) {
                const unsigned* wp = &sWt[(n * 8 + gid) * KP + kg + tid4];
                bf[n][0] = wp[0];
                bf[n][1] = wp[4];
            }

            unsigned af[2][4];
            #pragma unroll
            for (int m = 0; m < 2; m++) {
                int rb = warp * 32 + m * 16 + gid;
                const float* ap0 = &fb[rb * SFP + kl + tid4];
                const float* ap1 = &fb[(rb + 8) * SFP + kl + tid4];
                af[m][0] = f2tf32(ap0[0]);
                af[m][1] = f2tf32(ap1[0]);
                af[m][2] = f2tf32(ap0[4]);
                af[m][3] = f2tf32(ap1[4]);
            }

            #pragma unroll
            for (int n = 0; n < 4; n++)
                #pragma unroll
                for (int m = 0; m < 2; m++)
                    mma_tf32(acc[m][n][0], acc[m][n][1], acc[m][n][2], acc[m][n][3],
                             af[m][0], af[m][1], af[m][2], af[m][3],
                             bf[n][0], bf[n][1]);
        }
        __syncthreads();
    }

    #pragma unroll
    for (int m = 0; m < 2; m++) {
        int r0 = row0 + warp * 32 + m * 16 + gid;
        #pragma unroll
        for (int n = 0; n < 4; n++) {
            int col = n * 8 + 2 * tid4;
            if (r0 < n_nodes) {
                float2 v = make_float2(acc[m][n][0], acc[m][n][1]);
                *(float2*)(g_x + (size_t)r0 * OUT_FEAT + col) = v;
            }
            if (r0 + 8 < n_nodes) {
                float2 v = make_float2(acc[m][n][2], acc[m][n][3]);
                *(float2*)(g_x + (size_t)(r0 + 8) * OUT_FEAT + col) = v;
            }
        }
    }
}

// ---------------------------------------------------------------------------
// Stage 2a/2b: counter reset + bucketize (runs CONCURRENTLY with gemm)
// ---------------------------------------------------------------------------
__global__ void zero_kernel(int n) {
    int i = blockIdx.x * 256 + threadIdx.x;
    if (i < n) g_cnt[i] = 0;
    if (i == 0) g_ovf_n = 0;
}

__global__ __launch_bounds__(256)
void scatter_kernel(const float* __restrict__ vals,
                    const int* __restrict__ erow,
                    const int* __restrict__ ecol,
                    int n_edges) {
    int e = blockIdx.x * 256 + threadIdx.x;
    if (e >= n_edges) return;
    int r = erow[e];
    int pos = atomicAdd(&g_cnt[r], 1);
    if (pos < CAP) {
        g_bucket[(size_t)r * CAP + pos] =
            make_uint2((unsigned)ecol[e], __float_as_uint(vals[e]));
    } else {
        int o = atomicAdd(&g_ovf_n, 1);
        if (o < MAXOVF) g_ovf[o] = e;
    }
}

// ---------------------------------------------------------------------------
// Stage 2c: 8 threads per row, 4 cols each. No shuffles: each group re-loads
// the 8B pair (same addr -> broadcast), one float4 x-gather + 4 FFMA / edge,
// unrolled x4 for MLP. Writes every row -> no memset needed.
// ---------------------------------------------------------------------------
__global__ __launch_bounds__(256)
void gather_kernel(float* __restrict__ out, int n_nodes) {
    int idx = blockIdx.x * 256 + threadIdx.x;
    int row = idx >> 3;
    if (row >= n_nodes) return;
    int q = (idx & 7) << 2;

    int cnt = g_cnt[row];
    if (cnt > CAP) cnt = CAP;
    const uint2* bk = g_bucket + (size_t)row * CAP;

    float4 acc; acc.x = acc.y = acc.z = acc.w = 0.f;

    int j = 0;
    for (; j + 4 <= cnt; j += 4) {
        uint2 p0 = bk[j];
        uint2 p1 = bk[j + 1];
        uint2 p2 = bk[j + 2];
        uint2 p3 = bk[j + 3];
        float4 x0 = *(const float4*)(g_x + (size_t)p0.x * OUT_FEAT + q);
        float4 x1 = *(const float4*)(g_x + (size_t)p1.x * OUT_FEAT + q);
        float4 x2 = *(const float4*)(g_x + (size_t)p2.x * OUT_FEAT + q);
        float4 x3 = *(const float4*)(g_x + (size_t)p3.x * OUT_FEAT + q);
        float v0 = __uint_as_float(p0.y), v1 = __uint_as_float(p1.y);
        float v2 = __uint_as_float(p2.y), v3 = __uint_as_float(p3.y);
        acc.x += v0 * x0.x + v1 * x1.x + v2 * x2.x + v3 * x3.x;
        acc.y += v0 * x0.y + v1 * x1.y + v2 * x2.y + v3 * x3.y;
        acc.z += v0 * x0.z + v1 * x1.z + v2 * x2.z + v3 * x3.z;
        acc.w += v0 * x0.w + v1 * x1.w + v2 * x2.w + v3 * x3.w;
    }
    for (; j < cnt; j++) {
        uint2 p = bk[j];
        float4 xv = *(const float4*)(g_x + (size_t)p.x * OUT_FEAT + q);
        float v = __uint_as_float(p.y);
        acc.x += v * xv.x; acc.y += v * xv.y;
        acc.z += v * xv.z; acc.w += v * xv.w;
    }

    *(float4*)(out + (size_t)row * OUT_FEAT + q) = acc;
}

// ---------------------------------------------------------------------------
// Stage 2d: overflow fixup (expected empty; unconditional correctness)
// ---------------------------------------------------------------------------
__global__ void fixup_kernel(const float* __restrict__ vals,
                             const int* __restrict__ erow,
                             const int* __restrict__ ecol,
                             float* __restrict__ out) {
    int n = g_ovf_n;
    if (n > MAXOVF) n = MAXOVF;
    for (int i = threadIdx.x; i < n * 8; i += 256) {
        int e = g_ovf[i >> 3];
        int q = (i & 7) << 2;
        int r = erow[e], c = ecol[e];
        float v = vals[e];
        #pragma unroll
        for (int k = 0; k < 4; k++)
            atomicAdd(&out[(size_t)r * OUT_FEAT + q + k],
                      v * g_x[(size_t)c * OUT_FEAT + q + k]);
    }
}

// ---------------------------------------------------------------------------
extern "C" void kernel_launch(void* const* d_in, const int* in_sizes, int n_in,
                              void* d_out, int out_size) {
    const float* feat   = (const float*)d_in[0];
    const float* weight = (const float*)d_in[1];
    const float* vals   = (const float*)d_in[2];
    const int*   erow   = (const int*)d_in[3];
    const int*   ecol   = (const int*)d_in[4];
    float* out = (float*)d_out;

    int n_nodes = in_sizes[0] / IN_FEAT;
    int n_edges = in_sizes[2];

    // one-time host-side objects (no device memory involved)
    static cudaStream_t s2 = nullptr;
    static cudaEvent_t  evFork = nullptr, evJoin = nullptr;
    if (!s2) {
        cudaStreamCreateWithFlags(&s2, cudaStreamNonBlocking);
        cudaEventCreateWithFlags(&evFork, cudaEventDisableTiming);
        cudaEventCreateWithFlags(&evJoin, cudaEventDisableTiming);
    }

    cudaFuncSetAttribute(gemm_kernel,
                         cudaFuncAttributeMaxDynamicSharedMemorySize, SMEM_BYTES);

    int nb_nodes = (n_nodes + 255) / 256;
    int nb_edges = (n_edges + 255) / 256;
    int gemm_blocks = (n_nodes + TM - 1) / TM;

    // fork: bucket build runs on s2 concurrently with gemm on the main stream
    cudaEventRecord(evFork, 0);
    cudaStreamWaitEvent(s2, evFork, 0);

    gemm_kernel<<<gemm_blocks, NT, SMEM_BYTES>>>(feat, weight, n_nodes);

    zero_kernel<<<nb_nodes, 256, 0, s2>>>(n_nodes);
    scatter_kernel<<<nb_edges, 256, 0, s2>>>(vals, erow, ecol, n_edges);

    // join: gather needs both g_x (gemm) and buckets (scatter)
    cudaEventRecord(evJoin, s2);
    cudaStreamWaitEvent(0, evJoin, 0);

    long long gw = (long long)n_nodes * 8;
    int nb_gather = (int)((gw + 255) / 256);
    gather_kernel<<<nb_gather, 256>>>(out, n_nodes);

    fixup_kernel<<<1, 256>>>(vals, erow, ecol, out);
}